// round 12
// baseline (speedup 1.0000x reference)
#include <cuda_runtime.h>
#include <cstdint>

#define EMB 256
#define HID 64
#define MAXN 100000
#define MAXQ 8192
#define BCAP 64

// ---------------- scratch (device globals; zero-initialized) ----------------
__device__ int      g_slot[MAXN];          // node -> 0 or slot+1; restored each run
__device__ int      g_qslot[MAXQ];         // query i -> slot (winner index)
__device__ int      g_cnt[MAXQ];           // edges per slot
__device__ int2     g_bin[MAXQ][BCAP];     // (src, w bits) per slot
__device__ uint32_t g_atf[MAXQ][2 * EMB];  // A rows: [tf32 emb | tf32 agg]
__device__ float    g_c[MAXQ];             // per-slot sum_e w_e
__device__ uint32_t g_Wtf[2][HID * EMB];   // tf32-converted Ws, Wn

__device__ __forceinline__ uint32_t f2tf32(float x) {
    uint32_t r;
    asm("cvt.rna.tf32.f32 %0, %1;" : "=r"(r) : "f"(x));
    return r;
}
__device__ __forceinline__ uint4 tf4(float4 v) {
    return make_uint4(f2tf32(v.x), f2tf32(v.y), f2tf32(v.z), f2tf32(v.w));
}

// ---------------- k1: mark queries, zero counters, convert weights ----------------
__global__ void k_mark(const int* __restrict__ query,
                       const float* __restrict__ Ws,
                       const float* __restrict__ Wn, int Q) {
    int i = blockIdx.x * blockDim.x + threadIdx.x;     // 0..32767
    if (i < MAXQ) {
        g_cnt[i] = 0;
        if (i < Q) {
            int node = query[i];
            int old = atomicCAS(&g_slot[node], 0, i + 1);
            g_qslot[i] = (old == 0) ? i : (old - 1);
        }
    }
    if (i < HID * EMB) {
        g_Wtf[0][i] = f2tf32(Ws[i]);
        g_Wtf[1][i] = f2tf32(Wn[i]);
    }
}

// ---------------- k2: scan edges, bin hits by dst slot ----------------
__global__ void __launch_bounds__(256) k_filter(
    const int* __restrict__ src, const int* __restrict__ dst,
    const float* __restrict__ ew, int E)
{
    int e = blockIdx.x * blockDim.x + threadIdx.x;
    if (e >= E) return;
    int m = g_slot[dst[e]];
    if (m > 0) {
        int sl = m - 1;
        int pos = atomicAdd(&g_cnt[sl], 1);
        if (pos < BCAP) g_bin[sl][pos] = make_int2(src[e], __float_as_int(ew[e]));
    }
}

// ---------------- k3: warp per slot -> complete tf32 A row ----------------
__global__ void __launch_bounds__(256) k_accum(
    const float* __restrict__ emb, const int* __restrict__ query, int Q)
{
    int slot = (blockIdx.x * blockDim.x + threadIdx.x) >> 5;
    int lane = threadIdx.x & 31;
    if (slot >= Q) return;

    int cnt = min(g_cnt[slot], BCAP);
    const int2* bin = g_bin[slot];

    // emb half (issue these loads first; independent of the edge loop)
    const float4* er = (const float4*)(emb + (size_t)query[slot] * EMB);
    float4 e0 = er[lane], e1 = er[lane + 32];

    float4 acc0 = make_float4(0.f, 0.f, 0.f, 0.f);
    float4 acc1 = make_float4(0.f, 0.f, 0.f, 0.f);
    float  wsum = 0.f;

    int j = 0;
    for (; j + 2 <= cnt; j += 2) {
        int2 b0 = bin[j], b1 = bin[j + 1];
        float w0 = __int_as_float(b0.y), w1 = __int_as_float(b1.y);
        const float4* r0 = (const float4*)(emb + (size_t)b0.x * EMB);
        const float4* r1 = (const float4*)(emb + (size_t)b1.x * EMB);
        float4 v00 = r0[lane], v01 = r0[lane + 32];
        float4 v10 = r1[lane], v11 = r1[lane + 32];
        acc0.x = fmaf(w0, v00.x, acc0.x); acc0.y = fmaf(w0, v00.y, acc0.y);
        acc0.z = fmaf(w0, v00.z, acc0.z); acc0.w = fmaf(w0, v00.w, acc0.w);
        acc1.x = fmaf(w0, v01.x, acc1.x); acc1.y = fmaf(w0, v01.y, acc1.y);
        acc1.z = fmaf(w0, v01.z, acc1.z); acc1.w = fmaf(w0, v01.w, acc1.w);
        acc0.x = fmaf(w1, v10.x, acc0.x); acc0.y = fmaf(w1, v10.y, acc0.y);
        acc0.z = fmaf(w1, v10.z, acc0.z); acc0.w = fmaf(w1, v10.w, acc0.w);
        acc1.x = fmaf(w1, v11.x, acc1.x); acc1.y = fmaf(w1, v11.y, acc1.y);
        acc1.z = fmaf(w1, v11.z, acc1.z); acc1.w = fmaf(w1, v11.w, acc1.w);
        wsum += w0 + w1;
    }
    if (j < cnt) {
        int2 b0 = bin[j];
        float w0 = __int_as_float(b0.y);
        const float4* r0 = (const float4*)(emb + (size_t)b0.x * EMB);
        float4 v00 = r0[lane], v01 = r0[lane + 32];
        acc0.x = fmaf(w0, v00.x, acc0.x); acc0.y = fmaf(w0, v00.y, acc0.y);
        acc0.z = fmaf(w0, v00.z, acc0.z); acc0.w = fmaf(w0, v00.w, acc0.w);
        acc1.x = fmaf(w0, v01.x, acc1.x); acc1.y = fmaf(w0, v01.y, acc1.y);
        acc1.z = fmaf(w0, v01.z, acc1.z); acc1.w = fmaf(w0, v01.w, acc1.w);
        wsum += w0;
    }

    uint4* arow = (uint4*)g_atf[slot];       // 128 uint4: [0,64) emb, [64,128) agg
    arow[lane]           = tf4(e0);
    arow[lane + 32]      = tf4(e1);
    arow[64 + lane]      = tf4(acc0);
    arow[64 + 32 + lane] = tf4(acc1);
    if (lane == 0) g_c[slot] = wsum;
}

// ---------------- k4: tensor-core readout, all-cp.async, 4 blocks/SM ----------------
// out[q] = Wr . relu(Ws@emb[node_q] + Wn@agg_q + bs + c_q*bn) + br
// A = g_atf rows [32 q][512 k], B = g_Wtf [64 o][512 k]; 8 chunks of 64 k,
// A+B staged together per chunk, double-buffered. Inner: raw LDS + MMA.
#define QT     32
#define AROW   68
#define ACH    (QT * AROW)              // 2176 u32
#define BCH    (HID * AROW)             // 4352 u32
#define CHBUF  (ACH + BCH)              // 6528 u32 per stage buffer
#define AUX_O  (2 * CHBUF)              // + nodes[32] slots[32] csm[32] rsum[128]
#define RM_SMEM ((AUX_O + 224) * 4)     // ~53 KB -> 4 blocks/SM

__global__ void __launch_bounds__(256) k_readout_mma(
    const float* __restrict__ bs,  const float* __restrict__ bn,
    const float* __restrict__ Wr,  const float* __restrict__ br,
    const int* __restrict__ query, float* __restrict__ out, int Q)
{
    extern __shared__ float sm[];
    uint32_t* SB = (uint32_t*)sm;               // [2][CHBUF]: A then B
    int*   nodes = (int*)(sm + AUX_O);
    int*   slots = nodes + QT;
    float* csm   = (float*)(slots + QT);
    float* rsum  = csm + QT;                    // [4][QT]

    int tid   = threadIdx.x;
    int qbase = blockIdx.x * QT;

    if (tid < QT) {
        int q = qbase + tid;
        int sl = (q < Q) ? g_qslot[q] : 0;
        nodes[tid] = (q < Q) ? query[q] : query[0];
        slots[tid] = sl;
        csm[tid]   = g_c[sl];
    }
    __syncthreads();

    uint32_t smem_u32;
    asm("{ .reg .u64 t; cvta.to.shared.u64 t, %1; cvt.u32.u64 %0, t; }"
        : "=r"(smem_u32) : "l"(sm));

    // Stage chunk C (64 k-cols of A and B) into buffer BUF.
#define STAGE(C, BUF) { \
    _Pragma("unroll") \
    for (int it = 0; it < 2; ++it) { \
        int idx = tid + it * 256, row = idx >> 4, c4 = idx & 15; \
        const uint32_t* srcp = g_atf[slots[row]] + (C) * 64 + c4 * 4; \
        uint32_t dstp = smem_u32 + (uint32_t)((BUF) * CHBUF + row * AROW + c4 * 4) * 4u; \
        asm volatile("cp.async.cg.shared.global [%0], [%1], 16;" :: "r"(dstp), "l"(srcp)); \
    } \
    const uint32_t* Wp = g_Wtf[(C) < 4 ? 0 : 1]; \
    int kc = ((C) & 3) * 64; \
    _Pragma("unroll") \
    for (int it = 0; it < 4; ++it) { \
        int idx = tid + it * 256, o = idx >> 4, c4 = idx & 15; \
        const uint32_t* srcp = Wp + o * EMB + kc + c4 * 4; \
        uint32_t dstp = smem_u32 + (uint32_t)((BUF) * CHBUF + ACH + o * AROW + c4 * 4) * 4u; \
        asm volatile("cp.async.cg.shared.global [%0], [%1], 16;" :: "r"(dstp), "l"(srcp)); \
    } \
    asm volatile("cp.async.commit_group;"); }

    int lane = tid & 31;
    int wm = (tid >> 5) >> 2;            // 0..1 : q-range wm*16..+15
    int wn = (tid >> 5) & 3;             // 0..3 : o-range wn*16..+15
    int g  = lane >> 2, t = lane & 3;

    float acc[2][4];
#pragma unroll
    for (int a = 0; a < 2; ++a)
#pragma unroll
        for (int b = 0; b < 4; ++b) acc[a][b] = 0.f;

    STAGE(0, 0)

#pragma unroll
    for (int c = 0; c < 8; ++c) {
        if (c < 7) STAGE(c + 1, (c + 1) & 1)
        if (c < 7) { asm volatile("cp.async.wait_group 1;"); }
        else       { asm volatile("cp.async.wait_group 0;"); }
        __syncthreads();

        const uint32_t* ab = SB + (c & 1) * CHBUF + (wm * 16 + g) * AROW + t;
        const uint32_t* bb = SB + (c & 1) * CHBUF + ACH + (wn * 16 + g) * AROW + t;
#pragma unroll
        for (int ks = 0; ks < 8; ++ks) {
            int k0 = ks * 8;
            uint32_t a0 = ab[k0];
            uint32_t a1 = ab[k0 + 8 * AROW];
            uint32_t a2 = ab[k0 + 4];
            uint32_t a3 = ab[k0 + 8 * AROW + 4];
#pragma unroll
            for (int nt = 0; nt < 2; ++nt) {
                uint32_t b0 = bb[k0 + nt * 8 * AROW];
                uint32_t b1 = bb[k0 + nt * 8 * AROW + 4];
                asm("mma.sync.aligned.m16n8k8.row.col.f32.tf32.tf32.f32 "
                    "{%0,%1,%2,%3}, {%4,%5,%6,%7}, {%8,%9}, {%0,%1,%2,%3};"
                    : "+f"(acc[nt][0]), "+f"(acc[nt][1]),
                      "+f"(acc[nt][2]), "+f"(acc[nt][3])
                    : "r"(a0), "r"(a1), "r"(a2), "r"(a3), "r"(b0), "r"(b1));
            }
        }
        __syncthreads();
    }

    // Epilogue: rows q = wm*16+g (+8); cols o = wn*16 + nt*8 + 2t (+1)
    int qr0 = wm * 16 + g, qr1 = qr0 + 8;
    float cc0 = csm[qr0], cc1 = csm[qr1];
    float l0 = 0.f, l1 = 0.f;
#pragma unroll
    for (int nt = 0; nt < 2; ++nt) {
        int o0 = wn * 16 + nt * 8 + 2 * t;
        float b_s0 = bs[o0], b_s1 = bs[o0 + 1];
        float b_n0 = bn[o0], b_n1 = bn[o0 + 1];
        float w_r0 = Wr[o0], w_r1 = Wr[o0 + 1];
        l0 += w_r0 * fmaxf(acc[nt][0] + b_s0 + cc0 * b_n0, 0.f)
            + w_r1 * fmaxf(acc[nt][1] + b_s1 + cc0 * b_n1, 0.f);
        l1 += w_r0 * fmaxf(acc[nt][2] + b_s0 + cc1 * b_n0, 0.f)
            + w_r1 * fmaxf(acc[nt][3] + b_s1 + cc1 * b_n1, 0.f);
    }
    l0 += __shfl_xor_sync(0xffffffffu, l0, 1);
    l0 += __shfl_xor_sync(0xffffffffu, l0, 2);
    l1 += __shfl_xor_sync(0xffffffffu, l1, 1);
    l1 += __shfl_xor_sync(0xffffffffu, l1, 2);
    if (t == 0) {
        rsum[wn * QT + qr0] = l0;
        rsum[wn * QT + qr1] = l1;
    }
    __syncthreads();
    if (tid < QT) {
        int q = qbase + tid;
        if (q < Q) {
            out[q] = rsum[tid] + rsum[QT + tid] + rsum[2 * QT + tid]
                   + rsum[3 * QT + tid] + br[0];
            g_slot[nodes[tid]] = 0;     // restore for next replay (idempotent)
        }
    }
}

// ---------------- launch ----------------
extern "C" void kernel_launch(void* const* d_in, const int* in_sizes, int n_in,
                              void* d_out, int out_size) {
    const float* emb = (const float*)d_in[0];
    const float* ew  = (const float*)d_in[1];
    const float* Ws  = (const float*)d_in[2];
    const float* bs  = (const float*)d_in[3];
    const float* Wn  = (const float*)d_in[4];
    const float* bn  = (const float*)d_in[5];
    const float* Wr  = (const float*)d_in[6];
    const float* br  = (const float*)d_in[7];
    const int*   src = (const int*)d_in[8];
    const int*   dst = (const int*)d_in[9];
    const int*   qry = (const int*)d_in[10];

    int E = in_sizes[8];
    int Q = in_sizes[10];

    cudaFuncSetAttribute(k_readout_mma, cudaFuncAttributeMaxDynamicSharedMemorySize, RM_SMEM);

    k_mark       <<<128, 256>>>(qry, Ws, Wn, Q);
    k_filter     <<<(E + 255) / 256, 256>>>(src, dst, ew, E);
    k_accum      <<<(Q * 32 + 255) / 256, 256>>>(emb, qry, Q);
    k_readout_mma<<<(Q + QT - 1) / QT, 256, RM_SMEM>>>(bs, bn, Wr, br, qry,
                                                       (float*)d_out, Q);
}